// round 7
// baseline (speedup 1.0000x reference)
#include <cuda_runtime.h>
#include <cuda_bf16.h>
#include <cuda_fp8.h>
#include <stdint.h>

// ---------------- problem constants ----------------
#define I_N 1024
#define O_N 36
#define C_N 1024
#define W_N 60
#define D_N 64
#define MARGIN 0.2f

#define IMG_PER_CTA 7
#define NCTA 147            // ceil(1024/7)
#define THREADS 256         // 8 warps; warp w owns m16-tiles w and w+8 (256 rows)
#define CAP_BATCH 8         // captions per B buffer (4KB each, fp8)
#define NBATCH (C_N / CAP_BATCH)

// ---------------- smem layout (bytes from 1024-aligned base) ----------------
#define OFF_A    0          // 256 rows x 64B (fp8)              = 16384
#define OFF_B    16384      // 2 bufs x 32KB (8 captions each)   = 65536
#define OFF_RMAX 81920      // 8 x 256 floats                    = 8192
#define OFF_INV  90112      // 7 floats
#define SMEM_BYTES (90144 + 1024)

// ---------------- device globals ----------------
__device__ unsigned char gA [(size_t)I_N * O_N * D_N];  // e4m3, [row][k] 64B rows
__device__ unsigned char gB [(size_t)C_N * 64 * D_N];   // e4m3, [c][n][k]; words padded w/ dup of last valid
__device__ float g_scores[(size_t)I_N * C_N];
__device__ float g_diag[I_N];
__device__ float g_partial[I_N];

// ---------------- helpers ----------------
__device__ __forceinline__ uint32_t smem_u32(const void* p) {
    uint32_t a;
    asm("{ .reg .u64 t; cvta.to.shared.u64 t, %1; cvt.u32.u64 %0, t; }" : "=r"(a) : "l"(p));
    return a;
}
// 64B-row swizzle: XOR 16B-chunk index (bits 4-5) with row bits 1-2 (bits 7-8).
#define SW64(off) ((off) ^ (((off) >> 3) & 0x30))

__device__ __forceinline__ void ldsm4(uint32_t* r, uint32_t addr) {
    asm volatile("ldmatrix.sync.aligned.m8n8.x4.shared.b16 {%0,%1,%2,%3}, [%4];"
                 : "=r"(r[0]), "=r"(r[1]), "=r"(r[2]), "=r"(r[3]) : "r"(addr));
}
__device__ __forceinline__ void mma_fp8(float* d, const uint32_t* a, const uint32_t* b) {
    asm volatile(
        "mma.sync.aligned.m16n8k32.row.col.f32.e4m3.e4m3.f32 "
        "{%0,%1,%2,%3}, {%4,%5,%6,%7}, {%8,%9}, {%0,%1,%2,%3};"
        : "+f"(d[0]), "+f"(d[1]), "+f"(d[2]), "+f"(d[3])
        : "r"(a[0]), "r"(a[1]), "r"(a[2]), "r"(a[3]), "r"(b[0]), "r"(b[1]));
}
#define CP16(dst, src) \
    asm volatile("cp.async.cg.shared.global [%0], [%1], 16;" :: "r"(dst), "l"(src))
#define CP_COMMIT()  asm volatile("cp.async.commit_group;" ::: "memory")
#define CP_WAIT(n)   asm volatile("cp.async.wait_group %0;" :: "n"(n) : "memory")

// ---------------- precompute: fp32 -> e4m3 ----------------
extern "C" __global__ void convA_kernel(const float* __restrict__ im)
{
    size_t idx = (size_t)blockIdx.x * blockDim.x + threadIdx.x;
    if (idx >= (size_t)I_N * O_N * D_N) return;
    gA[idx] = __nv_cvt_float_to_fp8(im[idx], __NV_SATFINITE, __NV_E4M3);
}

// Pad words [clen, 64) with a COPY of word clen-1: max over any computed
// superset of columns equals the true max -> no masking needed downstream.
extern "C" __global__ void convB_kernel(const float* __restrict__ s,
                                        const int* __restrict__ s_l)
{
    size_t idx = (size_t)blockIdx.x * blockDim.x + threadIdx.x;
    if (idx >= (size_t)C_N * 64 * D_N) return;
    int d = idx & 63;
    int w = ((int)idx >> 6) & 63;
    int c = (int)(idx >> 12);
    int clen = s_l[c];
    int ws = (w < clen) ? w : (clen - 1);
    gB[idx] = __nv_cvt_float_to_fp8(s[((size_t)c * W_N + ws) * D_N + d],
                                    __NV_SATFINITE, __NV_E4M3);
}

// ---------------- main xattn-scores kernel (fp8 mma.sync) ----------------
extern "C" __global__ void __launch_bounds__(THREADS, 1)
xattn_kernel(const int* __restrict__ im_l, const int* __restrict__ s_l)
{
    extern __shared__ char smraw[];
    const uint32_t raw_u = smem_u32(smraw);
    const uint32_t abase = (raw_u + 1023u) & ~1023u;
    char* base = smraw + (abase - raw_u);

    const int tid  = threadIdx.x;
    const int wid  = tid >> 5;
    const int lane = tid & 31;
    const int img0 = blockIdx.x * IMG_PER_CTA;
    const int n_img = (I_N - img0 < IMG_PER_CTA) ? (I_N - img0) : IMG_PER_CTA;

    float* rmax = (float*)(base + OFF_RMAX);   // [8][256]
    float* inv  = (float*)(base + OFF_INV);
    if (tid < n_img)
        inv[tid] = 1.0f / ((float)im_l[img0 + tid] + 1e-6f);

    // ---- stage A into SW64 smem (256 rows x 64B); zero-pad rows >= n_img*36 ----
    {
        const int vchunks = n_img * O_N * 4;           // 16B chunks of valid rows
        const uint4* ga = (const uint4*)(gA + (size_t)img0 * O_N * D_N);
        const uint4 z = make_uint4(0, 0, 0, 0);
        #pragma unroll
        for (int t = tid; t < 1024; t += THREADS) {
            uint32_t off = SW64((uint32_t)(t * 16));
            *(uint4*)(base + OFF_A + off) = (t < vchunks) ? ga[t] : z;
        }
    }

    // ---- prefetch B batch 0 (captions 0..7): 32 KB ----
    {
        const char* sh = (const char*)(gB);
        uint32_t dst = abase + OFF_B;
        #pragma unroll
        for (int t = tid; t < 2048; t += THREADS) {
            uint32_t off = SW64((uint32_t)(t * 16));
            CP16(dst + off, sh + t * 16);
        }
    }
    CP_COMMIT();
    __syncthreads();

    // ---- A fragments: one ldsm4 per (m-tile, k-step), resident in regs ----
    // fp8 m16n8k32 A frag: a0 rows m0..7 k0-15 | a1 rows+8 k0-15 | a2 rows k16-31 | a3 rows+8 k16-31
    uint32_t af[2][2][4];
    #pragma unroll
    for (int m = 0; m < 2; ++m)
        #pragma unroll
        for (int ks = 0; ks < 2; ++ks) {
            uint32_t raw = (uint32_t)((wid * 16 + (lane & 15) + m * 128) * 64
                          + ks * 32 + ((lane >> 4) << 4));
            ldsm4(af[m][ks], abase + OFF_A + SW64(raw));
        }

    // B ldsm lane offset (constant across tiles/captions; tile stride 512B, caption 4KB)
    const uint32_t bloff = SW64((uint32_t)((lane & 7) * 64 + ((lane >> 3) << 4)));

    for (int cc = 0; cc < NBATCH; ++cc) {
        // prefetch next batch (32 KB)
        if (cc + 1 < NBATCH) {
            const char* sh = (const char*)(gB + (size_t)(cc + 1) * 32768);
            uint32_t dst = abase + OFF_B + (uint32_t)((cc + 1) & 1) * 32768;
            #pragma unroll
            for (int t = tid; t < 2048; t += THREADS) {
                uint32_t off = SW64((uint32_t)(t * 16));
                CP16(dst + off, sh + t * 16);
            }
            CP_COMMIT();
            CP_WAIT(1);
        } else {
            CP_WAIT(0);
        }
        __syncthreads();   // batch (cc) B ready; prev-batch rmax reads complete

        #pragma unroll
        for (int j = 0; j < CAP_BATCH; ++j) {
            const int c = CAP_BATCH * cc + j;
            const int clen = __ldg(&s_l[c]);
            const int nlim = (clen + 7) >> 3;      // n8 tiles to compute
            const uint32_t bh_base = abase + OFF_B + (uint32_t)((cc & 1) << 15)
                                    + (uint32_t)(j << 12) + bloff;

            float mx[4] = { -1e30f, -1e30f, -1e30f, -1e30f };

            #pragma unroll
            for (int p = 0; p < 4; ++p) {
                const int n0 = 2 * p;
                if (n0 < nlim) {
                    const bool has2 = (n0 + 1) < nlim;
                    // one ldsm4 per tile covers all k: r0,r1 = kstep0 {b0,b1}; r2,r3 = kstep1
                    uint32_t bf0[4], bf1[4];
                    ldsm4(bf0, bh_base + (uint32_t)(n0 * 512));
                    if (has2) ldsm4(bf1, bh_base + (uint32_t)((n0 + 1) * 512));

                    float acc[2][2][4];
                    #pragma unroll
                    for (int m = 0; m < 2; ++m)
                        #pragma unroll
                        for (int t2 = 0; t2 < 2; ++t2)
                            #pragma unroll
                            for (int q = 0; q < 4; ++q) acc[m][t2][q] = 0.0f;

                    #pragma unroll
                    for (int ks = 0; ks < 2; ++ks) {
                        mma_fp8(acc[0][0], af[0][ks], &bf0[2 * ks]);
                        mma_fp8(acc[1][0], af[1][ks], &bf0[2 * ks]);
                        if (has2) {
                            mma_fp8(acc[0][1], af[0][ks], &bf1[2 * ks]);
                            mma_fp8(acc[1][1], af[1][ks], &bf1[2 * ks]);
                        }
                    }

                    mx[0] = fmaxf(mx[0], fmaxf(acc[0][0][0], acc[0][0][1]));
                    mx[1] = fmaxf(mx[1], fmaxf(acc[0][0][2], acc[0][0][3]));
                    mx[2] = fmaxf(mx[2], fmaxf(acc[1][0][0], acc[1][0][1]));
                    mx[3] = fmaxf(mx[3], fmaxf(acc[1][0][2], acc[1][0][3]));
                    if (has2) {
                        mx[0] = fmaxf(mx[0], fmaxf(acc[0][1][0], acc[0][1][1]));
                        mx[1] = fmaxf(mx[1], fmaxf(acc[0][1][2], acc[0][1][3]));
                        mx[2] = fmaxf(mx[2], fmaxf(acc[1][1][0], acc[1][1][1]));
                        mx[3] = fmaxf(mx[3], fmaxf(acc[1][1][2], acc[1][1][3]));
                    }
                }
            }

            // quad reduce (lanes sharing the same rows)
            #pragma unroll
            for (int q = 0; q < 4; ++q) {
                mx[q] = fmaxf(mx[q], __shfl_xor_sync(0xFFFFFFFFu, mx[q], 1));
                mx[q] = fmaxf(mx[q], __shfl_xor_sync(0xFFFFFFFFu, mx[q], 2));
            }
            if ((lane & 3) == 0) {
                float* rj = rmax + j * 256;
                const int row0 = wid * 16 + (lane >> 2);
                rj[row0]       = mx[0];
                rj[row0 + 8]   = mx[1];
                rj[row0 + 128] = mx[2];
                rj[row0 + 136] = mx[3];
            }
        }
        __syncthreads();   // all 8 captions' rmax ready

        // ---- warp-parallel score epilogue: warp w reduces image w ----
        if (wid < n_img) {
            const float iv = inv[wid];
            const int rbase = wid * O_N;
            #pragma unroll
            for (int j = 0; j < CAP_BATCH; ++j) {
                float v = rmax[j * 256 + rbase + lane];
                if (lane < O_N - 32) v += rmax[j * 256 + rbase + 32 + lane];
                #pragma unroll
                for (int o = 16; o > 0; o >>= 1)
                    v += __shfl_xor_sync(0xFFFFFFFFu, v, o);
                if (lane == 0)
                    g_scores[(size_t)(img0 + wid) * C_N + CAP_BATCH * cc + j] = v * iv;
            }
        }
        // WAR on rmax covered by next batch's B-ready syncthreads
    }
}

// ---------------- loss epilogue ----------------
extern "C" __global__ void diag_kernel()
{
    int i = blockIdx.x * blockDim.x + threadIdx.x;
    if (i < I_N) g_diag[i] = g_scores[(size_t)i * C_N + i];
}

extern "C" __global__ void row_kernel()
{
    const int b = blockIdx.x;
    const int tid = threadIdx.x;
    const float di = g_diag[b];
    float local = 0.0f;
    for (int c = tid; c < C_N; c += blockDim.x) {
        if (c == b) continue;
        float sc = g_scores[(size_t)b * C_N + c];
        local += fmaxf(0.0f, MARGIN + sc - di)
               + fmaxf(0.0f, MARGIN + sc - g_diag[c]);
    }
    __shared__ float buf[128];
    buf[tid] = local;
    __syncthreads();
    for (int s = 64; s > 0; s >>= 1) {
        if (tid < s) buf[tid] += buf[tid + s];
        __syncthreads();
    }
    if (tid == 0) g_partial[b] = buf[0];
}

extern "C" __global__ void final_kernel(float* out)
{
    const int tid = threadIdx.x;
    float local = 0.0f;
    for (int i = tid; i < I_N; i += 256) local += g_partial[i];
    __shared__ float buf[256];
    buf[tid] = local;
    __syncthreads();
    for (int s = 128; s > 0; s >>= 1) {
        if (tid < s) buf[tid] += buf[tid + s];
        __syncthreads();
    }
    if (tid == 0) out[0] = buf[0] * (1.0f / ((float)I_N * (float)C_N));
}

// ---------------- launch ----------------
extern "C" void kernel_launch(void* const* d_in, const int* in_sizes, int n_in,
                              void* d_out, int out_size)
{
    const float* im   = (const float*)d_in[0];
    const float* s    = (const float*)d_in[1];
    const int*   im_l = (const int*)d_in[2];
    const int*   s_l  = (const int*)d_in[3];

    cudaFuncSetAttribute(xattn_kernel,
                         cudaFuncAttributeMaxDynamicSharedMemorySize, SMEM_BYTES);

    convA_kernel<<<(I_N * O_N * D_N + 255) / 256, 256>>>(im);
    convB_kernel<<<(C_N * 64 * D_N + 255) / 256, 256>>>(s, s_l);
    xattn_kernel<<<NCTA, THREADS, SMEM_BYTES>>>(im_l, s_l);
    diag_kernel<<<I_N / 256, 256>>>();
    row_kernel<<<I_N, 128>>>();
    final_kernel<<<1, 256>>>((float*)d_out);
}

// round 8
// speedup vs baseline: 1.4198x; 1.4198x over previous
#include <cuda_runtime.h>
#include <cuda_bf16.h>
#include <stdint.h>

// ---------------- problem constants ----------------
#define I_N 1024
#define O_N 36
#define C_N 1024
#define W_N 60
#define D_N 64
#define MARGIN 0.2f

#define IMG_PER_CTA 7
#define NCTA 147            // ceil(1024/7)
#define THREADS 512         // 16 warps; warp w owns m16-tile w (256 rows total)
#define CAP_BATCH 8         // captions per B buffer (8KB each, bf16)
#define NBATCH (C_N / CAP_BATCH)

// ---------------- smem layout (bytes from 1024-aligned base) ----------------
#define OFF_A    0          // 256 rows x 128B (bf16)            = 32768
#define OFF_B    32768      // 2 bufs x 64KB (8 captions each)   = 131072
#define OFF_RMAX 163840     // 8 x 256 floats                    = 8192
#define OFF_INV  172032     // 7 floats
#define SMEM_BYTES (172064 + 1024)

// ---------------- device globals ----------------
__device__ __nv_bfloat16 gA [(size_t)I_N * O_N * D_N];
__device__ __nv_bfloat16 gBh[(size_t)C_N * 64 * D_N];   // words padded to 64 w/ duplicate of last valid word
__device__ float g_scores[(size_t)I_N * C_N];
__device__ float g_diag[I_N];
__device__ float g_partial[I_N];

// ---------------- helpers ----------------
__device__ __forceinline__ uint32_t smem_u32(const void* p) {
    uint32_t a;
    asm("{ .reg .u64 t; cvta.to.shared.u64 t, %1; cvt.u32.u64 %0, t; }" : "=r"(a) : "l"(p));
    return a;
}
#define SW128(off) ((off) ^ (((off) >> 3) & 0x70))

__device__ __forceinline__ void ldsm4(uint32_t* r, uint32_t addr) {
    asm volatile("ldmatrix.sync.aligned.m8n8.x4.shared.b16 {%0,%1,%2,%3}, [%4];"
                 : "=r"(r[0]), "=r"(r[1]), "=r"(r[2]), "=r"(r[3]) : "r"(addr));
}
__device__ __forceinline__ void mma16816(float* d, const uint32_t* a, const uint32_t* b) {
    asm volatile(
        "mma.sync.aligned.m16n8k16.row.col.f32.bf16.bf16.f32 "
        "{%0,%1,%2,%3}, {%4,%5,%6,%7}, {%8,%9}, {%0,%1,%2,%3};"
        : "+f"(d[0]), "+f"(d[1]), "+f"(d[2]), "+f"(d[3])
        : "r"(a[0]), "r"(a[1]), "r"(a[2]), "r"(a[3]), "r"(b[0]), "r"(b[1]));
}
#define CP16(dst, src) \
    asm volatile("cp.async.cg.shared.global [%0], [%1], 16;" :: "r"(dst), "l"(src))
#define CP_COMMIT()  asm volatile("cp.async.commit_group;" ::: "memory")
#define CP_WAIT(n)   asm volatile("cp.async.wait_group %0;" :: "n"(n) : "memory")

// ---------------- precompute ----------------
extern "C" __global__ void convA_kernel(const float* __restrict__ im)
{
    size_t idx = (size_t)blockIdx.x * blockDim.x + threadIdx.x;
    if (idx >= (size_t)I_N * O_N * D_N) return;
    gA[idx] = __float2bfloat16(im[idx]);
}

// Pad words [clen, 64) with a COPY of word clen-1: max over any computed
// superset of columns equals the true max -> no masking needed downstream.
extern "C" __global__ void convB_kernel(const float* __restrict__ s,
                                        const int* __restrict__ s_l)
{
    size_t idx = (size_t)blockIdx.x * blockDim.x + threadIdx.x;
    if (idx >= (size_t)C_N * 64 * D_N) return;
    int d = idx & 63;
    int w = ((int)idx >> 6) & 63;
    int c = (int)(idx >> 12);
    int clen = s_l[c];
    int ws = (w < clen) ? w : (clen - 1);
    gBh[idx] = __float2bfloat16(s[((size_t)c * W_N + ws) * D_N + d]);
}

// ---------------- main xattn-scores kernel ----------------
extern "C" __global__ void __launch_bounds__(THREADS, 1)
xattn_kernel(const int* __restrict__ im_l, const int* __restrict__ s_l)
{
    extern __shared__ char smraw[];
    const uint32_t raw_u = smem_u32(smraw);
    const uint32_t abase = (raw_u + 1023u) & ~1023u;
    char* base = smraw + (abase - raw_u);

    const int tid  = threadIdx.x;
    const int wid  = tid >> 5;          // 0..15, owns m16-tile wid
    const int lane = tid & 31;
    const int img0 = blockIdx.x * IMG_PER_CTA;
    const int n_img = (I_N - img0 < IMG_PER_CTA) ? (I_N - img0) : IMG_PER_CTA;

    float* rmax = (float*)(base + OFF_RMAX);   // [8][256]
    float* inv  = (float*)(base + OFF_INV);
    if (tid < n_img)
        inv[tid] = 1.0f / ((float)im_l[img0 + tid] + 1e-6f);

    // ---- stage A into swizzled smem; zero-pad rows >= n_img*36 ----
    {
        const int vchunks = n_img * O_N * 8;
        const uint4* ga = (const uint4*)(gA + (size_t)img0 * O_N * D_N);
        const uint4 z = make_uint4(0, 0, 0, 0);
        #pragma unroll
        for (int t = tid; t < 2048; t += THREADS) {
            uint32_t off = SW128((uint32_t)(t * 16));
            *(uint4*)(base + OFF_A + off) = (t < vchunks) ? ga[t] : z;
        }
    }

    // ---- prefetch B batch 0 (captions 0..7): 64 KB ----
    {
        const char* sh = (const char*)(gBh);
        uint32_t dst = abase + OFF_B;
        #pragma unroll
        for (int t = tid; t < 4096; t += THREADS) {
            uint32_t off = SW128((uint32_t)(t * 16));
            CP16(dst + off, sh + t * 16);
        }
    }
    CP_COMMIT();
    __syncthreads();

    // ---- ldmatrix addressing invariants ----
    const uint32_t xr    = (uint32_t)((lane & 7) << 4);
    const uint32_t aColB = (uint32_t)((lane >> 4) << 4);
    const uint32_t aRow  = (uint32_t)(wid * 16 + (lane & 15));
    // B ldsm4: lane L -> row (L&7), matrix (L>>3); one x4 covers 2 k-steps.
    const uint32_t bRowOff = (uint32_t)((lane & 7) * 128);
    const uint32_t bMat    = (uint32_t)((lane >> 3) << 4);

    // ---- A fragments resident in registers (one m-tile per warp) ----
    uint32_t af[4][4];
    #pragma unroll
    for (int k = 0; k < 4; ++k)
        ldsm4(af[k], abase + OFF_A + aRow * 128 + ((aColB + (uint32_t)(k * 32)) ^ xr));

    for (int cc = 0; cc < NBATCH; ++cc) {
        // prefetch next batch (64 KB)
        if (cc + 1 < NBATCH) {
            const char* sh = (const char*)(gBh + (size_t)(cc + 1) * 32768);
            uint32_t dst = abase + OFF_B + (uint32_t)((cc + 1) & 1) * 65536;
            #pragma unroll
            for (int t = tid; t < 4096; t += THREADS) {
                uint32_t off = SW128((uint32_t)(t * 16));
                CP16(dst + off, sh + t * 16);
            }
            CP_COMMIT();
            CP_WAIT(1);
        } else {
            CP_WAIT(0);
        }
        __syncthreads();   // batch (cc) B ready; prev-batch rmax reads complete

        #pragma unroll
        for (int j = 0; j < CAP_BATCH; ++j) {
            const int c = CAP_BATCH * cc + j;
            const int clen = __ldg(&s_l[c]);
            const int nlim = (clen + 7) >> 3;      // n8 tiles to compute
            const uint32_t bh_base = abase + OFF_B + (uint32_t)((cc & 1) << 16)
                                    + (uint32_t)(j << 13);

            float mx[2] = { -1e30f, -1e30f };

            #pragma unroll
            for (int p = 0; p < 4; ++p) {
                const int n0 = 2 * p;
                if (n0 < nlim) {
                    const bool has2 = (n0 + 1) < nlim;
                    // bf[kp][0..3]: {r0,r1}=k-step 2kp, {r2,r3}=k-step 2kp+1
                    uint32_t bf0[2][4], bf1[2][4];
                    #pragma unroll
                    for (int kp = 0; kp < 2; ++kp)
                        ldsm4(bf0[kp], bh_base + (uint32_t)(n0 * 1024) + bRowOff
                                      + (((uint32_t)(kp * 64) + bMat) ^ xr));
                    if (has2) {
                        #pragma unroll
                        for (int kp = 0; kp < 2; ++kp)
                            ldsm4(bf1[kp], bh_base + (uint32_t)((n0 + 1) * 1024) + bRowOff
                                          + (((uint32_t)(kp * 64) + bMat) ^ xr));
                    }

                    float acc[2][4];
                    #pragma unroll
                    for (int t2 = 0; t2 < 2; ++t2)
                        #pragma unroll
                        for (int q = 0; q < 4; ++q) acc[t2][q] = 0.0f;

                    #pragma unroll
                    for (int k = 0; k < 4; ++k) {
                        mma16816(acc[0], af[k], &bf0[k >> 1][(k & 1) * 2]);
                        if (has2)
                            mma16816(acc[1], af[k], &bf1[k >> 1][(k & 1) * 2]);
                    }

                    mx[0] = fmaxf(mx[0], fmaxf(acc[0][0], acc[0][1]));
                    mx[1] = fmaxf(mx[1], fmaxf(acc[0][2], acc[0][3]));
                    if (has2) {
                        mx[0] = fmaxf(mx[0], fmaxf(acc[1][0], acc[1][1]));
                        mx[1] = fmaxf(mx[1], fmaxf(acc[1][2], acc[1][3]));
                    }
                }
            }

            // quad reduce (lanes sharing the same rows)
            #pragma unroll
            for (int q = 0; q < 2; ++q) {
                mx[q] = fmaxf(mx[q], __shfl_xor_sync(0xFFFFFFFFu, mx[q], 1));
                mx[q] = fmaxf(mx[q], __shfl_xor_sync(0xFFFFFFFFu, mx[q], 2));
            }
            if ((lane & 3) == 0) {
                float* rj = rmax + j * 256;
                const int row0 = wid * 16 + (lane >> 2);
                rj[row0]     = mx[0];
                rj[row0 + 8] = mx[1];
            }
        }
        __syncthreads();   // all 8 captions' rmax ready

        // ---- warp-parallel score epilogue: warp w reduces image w ----
        if (wid < n_img) {
            const float iv = inv[wid];
            const int rbase = wid * O_N;
            #pragma unroll
            for (int j = 0; j < CAP_BATCH; ++j) {
                float v = rmax[j * 256 + rbase + lane];
                if (lane < O_N - 32) v += rmax[j * 256 + rbase + 32 + lane];
                #pragma unroll
                for (int o = 16; o > 0; o >>= 1)
                    v += __shfl_xor_sync(0xFFFFFFFFu, v, o);
                if (lane == 0)
                    g_scores[(size_t)(img0 + wid) * C_N + CAP_BATCH * cc + j] = v * iv;
            }
        }
        // WAR on rmax covered by next batch's B-ready syncthreads
    }
}

// ---------------- loss epilogue ----------------
extern "C" __global__ void diag_kernel()
{
    int i = blockIdx.x * blockDim.x + threadIdx.x;
    if (i < I_N) g_diag[i] = g_scores[(size_t)i * C_N + i];
}

extern "C" __global__ void row_kernel()
{
    const int b = blockIdx.x;
    const int tid = threadIdx.x;
    const float di = g_diag[b];
    float local = 0.0f;
    for (int c = tid; c < C_N; c += blockDim.x) {
        if (c == b) continue;
        float sc = g_scores[(size_t)b * C_N + c];
        local += fmaxf(0.0f, MARGIN + sc - di)
               + fmaxf(0.0f, MARGIN + sc - g_diag[c]);
    }
    __shared__ float buf[128];
    buf[tid] = local;
    __syncthreads();
    for (int s = 64; s > 0; s >>= 1) {
        if (tid < s) buf[tid] += buf[tid + s];
        __syncthreads();
    }
    if (tid == 0) g_partial[b] = buf[0];
}

extern "C" __global__ void final_kernel(float* out)
{
    const int tid = threadIdx.x;
    float local = 0.0f;
    for (int i = tid; i < I_N; i += 256) local += g_partial[i];
    __shared__ float buf[256];
    buf[tid] = local;
    __syncthreads();
    for (int s = 128; s > 0; s >>= 1) {
        if (tid < s) buf[tid] += buf[tid + s];
        __syncthreads();
    }
    if (tid == 0) out[0] = buf[0] * (1.0f / ((float)I_N * (float)C_N));
}

// ---------------- launch ----------------
extern "C" void kernel_launch(void* const* d_in, const int* in_sizes, int n_in,
                              void* d_out, int out_size)
{
    const float* im   = (const float*)d_in[0];
    const float* s    = (const float*)d_in[1];
    const int*   im_l = (const int*)d_in[2];
    const int*   s_l  = (const int*)d_in[3];

    cudaFuncSetAttribute(xattn_kernel,
                         cudaFuncAttributeMaxDynamicSharedMemorySize, SMEM_BYTES);

    convA_kernel<<<(I_N * O_N * D_N + 255) / 256, 256>>>(im);
    convB_kernel<<<(C_N * 64 * D_N + 255) / 256, 256>>>(s, s_l);
    xattn_kernel<<<NCTA, THREADS, SMEM_BYTES>>>(im_l, s_l);
    diag_kernel<<<I_N / 256, 256>>>();
    row_kernel<<<I_N, 128>>>();
    final_kernel<<<1, 256>>>((float*)d_out);
}